// round 2
// baseline (speedup 1.0000x reference)
#include <cuda_runtime.h>
#include <math.h>

#define BS 2
#define DD 512
#define NN 65536
#define RR 64
#define EPSF 1e-6f

// ---------------- device scratch ----------------
__device__ float g_b0[BS*DD*RR];
__device__ float g_b1[BS*DD*RR];
__device__ float g_c[(size_t)BS*NN*RR];      // 32 MB
__device__ float g_BtB[BS*RR*RR];
__device__ float g_CtC[BS*RR*RR];
__device__ float g_numB[BS*DD*RR];

__device__ __forceinline__ float* bsel(int s){ return s ? g_b1 : g_b0; }

// ---------------- normalize bases over D ----------------
__global__ void __launch_bounds__(128) k_normb(const float* __restrict__ bases){
    int bs = blockIdx.x >> 6, r = blockIdx.x & 63;
    int tid = threadIdx.x;
    __shared__ float red[128];
    float s = 0.f;
    for (int d = tid; d < DD; d += 128){
        float v = bases[(bs*DD + d)*RR + r];
        s += v*v;
    }
    red[tid] = s; __syncthreads();
    for (int o = 64; o > 0; o >>= 1){ if (tid < o) red[tid] += red[tid+o]; __syncthreads(); }
    float inv = 1.f / fmaxf(sqrtf(red[0]), 1e-12f);
    for (int d = tid; d < DD; d += 128)
        g_b0[(bs*DD + d)*RR + r] = bases[(bs*DD + d)*RR + r] * inv;
}

// ---------------- BtB = b^T b ----------------
__global__ void __launch_bounds__(256) k_btb(int sel){
    const float* bb = bsel(sel) + blockIdx.y*DD*RR;
    int p = blockIdx.x*256 + threadIdx.x;   // 16 x-blocks -> 4096 outputs
    int r = p & 63, s = p >> 6;
    float acc = 0.f;
    for (int d = 0; d < DD; d++)
        acc = fmaf(bb[d*RR+r], bb[d*RR+s], acc);
    g_BtB[blockIdx.y*RR*RR + p] = acc;
}

// ---------------- zero CtC + numB accumulators ----------------
__global__ void k_zero(){
    int i = blockIdx.x*256 + threadIdx.x;
    if (i < BS*RR*RR) g_CtC[i] = 0.f;
    if (i < BS*DD*RR) g_numB[i] = 0.f;
}

// ---------------- shared GEMM core: acc += x(^T clamped?) * b, 64n x 64r, K=512 ----------------
template<bool CLAMPX>
__device__ __forceinline__ void gemmA(const float* __restrict__ x, const float* __restrict__ b,
                                      int bs, int n0, float acc[4][4],
                                      float (*xs)[64], float (*bsm)[64])
{
    int tid = threadIdx.x;
    int tr = tid & 15, tn = tid >> 4;
    int li = tid >> 4, lj = (tid & 15)*4;
    const float* xb = x + (size_t)bs*DD*NN + n0;
    const float* bb = b + bs*DD*RR;
    for (int kc = 0; kc < DD; kc += 16){
        float4 xv = *(const float4*)(xb + (size_t)(kc+li)*NN + lj);
        if (CLAMPX){
            xv.x=fmaxf(xv.x,EPSF); xv.y=fmaxf(xv.y,EPSF);
            xv.z=fmaxf(xv.z,EPSF); xv.w=fmaxf(xv.w,EPSF);
        }
        float4 bv = *(const float4*)(bb + (kc+li)*RR + lj);
        __syncthreads();
        *(float4*)&xs[li][lj]  = xv;
        *(float4*)&bsm[li][lj] = bv;
        __syncthreads();
        #pragma unroll
        for (int k = 0; k < 16; k++){
            float4 xr = *(const float4*)&xs[k][tn*4];
            float4 br = *(const float4*)&bsm[k][tr*4];
            float xa[4] = {xr.x,xr.y,xr.z,xr.w};
            float ba[4] = {br.x,br.y,br.z,br.w};
            #pragma unroll
            for (int a = 0; a < 4; a++)
                #pragma unroll
                for (int c = 0; c < 4; c++)
                    acc[a][c] = fmaf(xa[a], ba[c], acc[a][c]);
        }
    }
}

// MODE: 0 = init coef (softmax, unclamped x), 1 = MU c-step (+CtC), 2 = final c_new
template<int MODE>
__global__ void __launch_bounds__(256) k_cupdate(const float* __restrict__ x, int sel, int clampc){
    __shared__ float xs[16][64];
    __shared__ float bsm[16][64];
    __shared__ float BtBs[RR*RR];
    __shared__ float cs[64][68];
    int bs = blockIdx.y, n0 = blockIdx.x*64;
    int tid = threadIdx.x, tr = tid & 15, tn = tid >> 4;
    float* cb = g_c + ((size_t)bs*NN + n0)*RR;

    if (MODE != 0){
        for (int i = tid; i < RR*RR; i += 256) BtBs[i] = g_BtB[bs*RR*RR + i];
        for (int i = tid; i < 64*64; i += 256){
            int n = i >> 6, r = i & 63;
            float v = cb[n*RR + r];
            cs[n][r] = clampc ? fmaxf(v, EPSF) : v;
        }
        // gemmA's first __syncthreads orders these fills before any reads
    }

    float acc[4][4] = {};
    gemmA<(MODE!=0)>(x, bsel(sel), bs, n0, acc, xs, bsm);

    if (MODE == 0){
        // softmax over r (R=64) per n-row
        #pragma unroll
        for (int a = 0; a < 4; a++){
            float m = fmaxf(fmaxf(acc[a][0],acc[a][1]), fmaxf(acc[a][2],acc[a][3]));
            #pragma unroll
            for (int o = 1; o < 16; o <<= 1) m = fmaxf(m, __shfl_xor_sync(0xffffffffu, m, o));
            float e0 = __expf(acc[a][0]-m), e1 = __expf(acc[a][1]-m);
            float e2 = __expf(acc[a][2]-m), e3 = __expf(acc[a][3]-m);
            float s = e0+e1+e2+e3;
            #pragma unroll
            for (int o = 1; o < 16; o <<= 1) s += __shfl_xor_sync(0xffffffffu, s, o);
            float inv = 1.f / s;
            *(float4*)(cb + (tn*4+a)*RR + tr*4) = make_float4(e0*inv, e1*inv, e2*inv, e3*inv);
        }
        return;
    }

    // denC = c . BtB
    float den[4][4] = {};
    #pragma unroll 4
    for (int s = 0; s < RR; s++){
        float4 bt = *(const float4*)&BtBs[s*RR + tr*4];
        float cv[4];
        #pragma unroll
        for (int a = 0; a < 4; a++) cv[a] = cs[tn*4+a][s];
        #pragma unroll
        for (int a = 0; a < 4; a++){
            den[a][0] = fmaf(cv[a], bt.x, den[a][0]);
            den[a][1] = fmaf(cv[a], bt.y, den[a][1]);
            den[a][2] = fmaf(cv[a], bt.z, den[a][2]);
            den[a][3] = fmaf(cv[a], bt.w, den[a][3]);
        }
    }
    float cnew[4][4];
    #pragma unroll
    for (int a = 0; a < 4; a++)
        #pragma unroll
        for (int c = 0; c < 4; c++)
            cnew[a][c] = cs[tn*4+a][tr*4+c] * acc[a][c] / (den[a][c] + EPSF);

    __syncthreads();   // all cs reads for denC done
    #pragma unroll
    for (int a = 0; a < 4; a++){
        float4 w = make_float4(cnew[a][0], cnew[a][1], cnew[a][2], cnew[a][3]);
        *(float4*)(cb + (tn*4+a)*RR + tr*4) = w;   // store UNCLAMPED c'
        if (MODE == 1) *(float4*)&cs[tn*4+a][tr*4] = w;
    }
    if (MODE == 2) return;
    __syncthreads();

    // CtC partial over this 64-n tile: rows r = tr*4.., cols s = tn*4..
    float ct[4][4] = {};
    #pragma unroll 4
    for (int n = 0; n < 64; n++){
        float4 cr  = *(const float4*)&cs[n][tr*4];
        float4 csv = *(const float4*)&cs[n][tn*4];
        float a_[4] = {cr.x,cr.y,cr.z,cr.w};
        float b_[4] = {csv.x,csv.y,csv.z,csv.w};
        #pragma unroll
        for (int i = 0; i < 4; i++)
            #pragma unroll
            for (int j = 0; j < 4; j++)
                ct[i][j] = fmaf(a_[i], b_[j], ct[i][j]);
    }
    float* ctc = g_CtC + bs*RR*RR;
    #pragma unroll
    for (int i = 0; i < 4; i++)
        #pragma unroll
        for (int j = 0; j < 4; j++)
            atomicAdd(&ctc[(tr*4+i)*RR + tn*4+j], ct[i][j]);
}

// ---------------- numB = clamp(x) . c'  (split-K over N, atomic combine) ----------------
__global__ void __launch_bounds__(256) k_numB(const float* __restrict__ x){
    __shared__ float xs[16][132];   // [n][d], padded, float4-aligned rows
    __shared__ float cs[16][64];
    int bs = blockIdx.z;
    int d0 = blockIdx.y * 128;
    int nbase = blockIdx.x * 2048;
    int tid = threadIdx.x;
    int dl = tid >> 1, nc = (tid & 1) * 8;
    int rq = tid & 15, dg = tid >> 4;
    const float* xb = x + (size_t)bs*DD*NN;
    const float* cbase = g_c + (size_t)bs*NN*RR;
    float acc[8][4] = {};
    for (int nt = nbase; nt < nbase + 2048; nt += 16){
        float4 v0 = *(const float4*)(xb + (size_t)(d0+dl)*NN + nt + nc);
        float4 v1 = *(const float4*)(xb + (size_t)(d0+dl)*NN + nt + nc + 4);
        float4 cv = *(const float4*)(cbase + (size_t)(nt + (tid>>4))*RR + (tid&15)*4);
        __syncthreads();
        xs[nc+0][dl] = fmaxf(v0.x,EPSF); xs[nc+1][dl] = fmaxf(v0.y,EPSF);
        xs[nc+2][dl] = fmaxf(v0.z,EPSF); xs[nc+3][dl] = fmaxf(v0.w,EPSF);
        xs[nc+4][dl] = fmaxf(v1.x,EPSF); xs[nc+5][dl] = fmaxf(v1.y,EPSF);
        xs[nc+6][dl] = fmaxf(v1.z,EPSF); xs[nc+7][dl] = fmaxf(v1.w,EPSF);
        *(float4*)&cs[tid>>4][(tid&15)*4] = cv;
        __syncthreads();
        #pragma unroll
        for (int n = 0; n < 16; n++){
            float4 c4 = *(const float4*)&cs[n][rq*4];
            float4 x0 = *(const float4*)&xs[n][dg*8];
            float4 x1 = *(const float4*)&xs[n][dg*8+4];
            float xa[8] = {x0.x,x0.y,x0.z,x0.w,x1.x,x1.y,x1.z,x1.w};
            float ca[4] = {c4.x,c4.y,c4.z,c4.w};
            #pragma unroll
            for (int i = 0; i < 8; i++)
                #pragma unroll
                for (int j = 0; j < 4; j++)
                    acc[i][j] = fmaf(xa[i], ca[j], acc[i][j]);
        }
    }
    float* nb = g_numB + bs*DD*RR;
    #pragma unroll
    for (int i = 0; i < 8; i++)
        #pragma unroll
        for (int j = 0; j < 4; j++)
            atomicAdd(&nb[(d0 + dg*8 + i)*RR + rq*4 + j], acc[i][j]);
}

// ---------------- b update: denB, multiply, clamp, L2-normalize ----------------
__global__ void __launch_bounds__(128) k_bupdate(int selIn, int selOut){
    int r = blockIdx.x, bs = blockIdx.y;
    int tid = threadIdx.x;
    __shared__ float ctcCol[64];
    __shared__ float red[128];
    const float* bin  = bsel(selIn)  + bs*DD*RR;
    float*       bout = bsel(selOut) + bs*DD*RR;
    const float* nb   = g_numB + bs*DD*RR;
    if (tid < 64) ctcCol[tid] = g_CtC[bs*RR*RR + tid*RR + r];
    __syncthreads();
    float v[4], ss = 0.f;
    #pragma unroll
    for (int q = 0; q < 4; q++){
        int d = tid + q*128;
        const float* brow = bin + d*RR;
        float den = EPSF;
        #pragma unroll 8
        for (int s = 0; s < RR; s++) den = fmaf(brow[s], ctcCol[s], den);
        float t = fmaxf(brow[r] * nb[d*RR + r] / den, EPSF);
        v[q] = t; ss += t*t;
    }
    red[tid] = ss; __syncthreads();
    for (int o = 64; o > 0; o >>= 1){ if (tid < o) red[tid] += red[tid+o]; __syncthreads(); }
    float inv = 1.f / fmaxf(sqrtf(red[0]), 1e-12f);
    #pragma unroll
    for (int q = 0; q < 4; q++)
        bout[(tid + q*128)*RR + r] = v[q] * inv;
}

// ---------------- x_hat = b @ c_new^T ----------------
__global__ void __launch_bounds__(256) k_xhat(float* __restrict__ out, int sel){
    __shared__ float bt[64][68];   // [r][d]
    __shared__ float ct2[64][68];  // [r][n]
    int bs = blockIdx.z;
    int d0 = blockIdx.y * 64;
    int n0 = blockIdx.x * 64;
    int tid = threadIdx.x;
    const float* bb = bsel(sel) + bs*DD*RR;
    const float* cb = g_c + (size_t)bs*NN*RR;
    int rq = tid & 15, gi = tid >> 4;
    #pragma unroll
    for (int it = 0; it < 4; it++){
        int d = gi + it*16;
        float4 bv = *(const float4*)(bb + (d0+d)*RR + rq*4);
        bt[rq*4+0][d] = bv.x; bt[rq*4+1][d] = bv.y; bt[rq*4+2][d] = bv.z; bt[rq*4+3][d] = bv.w;
        int n = gi + it*16;
        float4 cv = *(const float4*)(cb + (size_t)(n0+n)*RR + rq*4);
        ct2[rq*4+0][n] = cv.x; ct2[rq*4+1][n] = cv.y; ct2[rq*4+2][n] = cv.z; ct2[rq*4+3][n] = cv.w;
    }
    __syncthreads();
    int dq = tid >> 4, nq = tid & 15;
    float acc[4][4] = {};
    #pragma unroll 8
    for (int r = 0; r < RR; r++){
        float4 bv = *(const float4*)&bt[r][dq*4];
        float4 cv = *(const float4*)&ct2[r][nq*4];
        float ba[4] = {bv.x,bv.y,bv.z,bv.w};
        float ca[4] = {cv.x,cv.y,cv.z,cv.w};
        #pragma unroll
        for (int i = 0; i < 4; i++)
            #pragma unroll
            for (int j = 0; j < 4; j++)
                acc[i][j] = fmaf(ba[i], ca[j], acc[i][j]);
    }
    #pragma unroll
    for (int i = 0; i < 4; i++)
        *(float4*)(out + (size_t)(bs*DD + d0 + dq*4 + i)*NN + n0 + nq*4) =
            make_float4(acc[i][0], acc[i][1], acc[i][2], acc[i][3]);
}

// ---------------- orchestration ----------------
extern "C" void kernel_launch(void* const* d_in, const int* in_sizes, int n_in,
                              void* d_out, int out_size){
    const float* x     = (const float*)d_in[0];
    const float* bases = (const float*)d_in[1];
    float* out = (float*)d_out;

    k_normb<<<BS*RR, 128>>>(bases);
    int sel = 0;

    // coef init: softmax(x^T b), unclamped x
    k_cupdate<0><<<dim3(NN/64, BS), 256>>>(x, sel, 0);

    for (int step = 0; step < 6; step++){
        int clampc = (step > 0) ? 1 : 0;
        k_btb<<<dim3(16, BS), 256>>>(sel);
        k_zero<<<288, 256>>>();
        k_cupdate<1><<<dim3(NN/64, BS), 256>>>(x, sel, clampc);
        k_numB<<<dim3(32, DD/128, BS), 256>>>(x);
        k_bupdate<<<dim3(RR, BS), 128>>>(sel, 1 - sel);
        sel = 1 - sel;
    }

    // final: c_new = coef * numC/denC, then x_hat = b @ c_new^T
    k_btb<<<dim3(16, BS), 256>>>(sel);
    k_cupdate<2><<<dim3(NN/64, BS), 256>>>(x, sel, 1);
    k_xhat<<<dim3(NN/64, DD/64, BS), 256>>>(out, sel);
}

// round 3
// speedup vs baseline: 1.0021x; 1.0021x over previous
#include <cuda_runtime.h>
#include <math.h>

#define BS 2
#define DD 512
#define NN 65536
#define RR 64
#define EPSF 1e-6f

// ---------------- device scratch ----------------
__device__ float g_b0[BS*DD*RR];
__device__ float g_b1[BS*DD*RR];
__device__ float g_c[(size_t)BS*NN*RR];      // 32 MB
__device__ float g_BtB[BS*RR*RR];
__device__ float g_CtC[BS*RR*RR];
__device__ float g_numB[BS*DD*RR];

__device__ __forceinline__ float* bsel(int s){ return s ? g_b1 : g_b0; }

// ---------------- normalize bases over D ----------------
__global__ void __launch_bounds__(128) k_normb(const float* __restrict__ bases){
    int bs = blockIdx.x >> 6, r = blockIdx.x & 63;
    int tid = threadIdx.x;
    __shared__ float red[128];
    float s = 0.f;
    for (int d = tid; d < DD; d += 128){
        float v = bases[(bs*DD + d)*RR + r];
        s += v*v;
    }
    red[tid] = s; __syncthreads();
    for (int o = 64; o > 0; o >>= 1){ if (tid < o) red[tid] += red[tid+o]; __syncthreads(); }
    float inv = 1.f / fmaxf(sqrtf(red[0]), 1e-12f);
    for (int d = tid; d < DD; d += 128)
        g_b0[(bs*DD + d)*RR + r] = bases[(bs*DD + d)*RR + r] * inv;
}

// ---------------- BtB = b^T b ----------------
__global__ void __launch_bounds__(256) k_btb(int sel){
    const float* bb = bsel(sel) + blockIdx.y*DD*RR;
    int p = blockIdx.x*256 + threadIdx.x;   // 16 x-blocks -> 4096 outputs
    int r = p & 63, s = p >> 6;
    float acc = 0.f;
    for (int d = 0; d < DD; d++)
        acc = fmaf(bb[d*RR+r], bb[d*RR+s], acc);
    g_BtB[blockIdx.y*RR*RR + p] = acc;
}

// ---------------- zero CtC + numB accumulators ----------------
__global__ void k_zero(){
    int i = blockIdx.x*256 + threadIdx.x;
    if (i < BS*RR*RR) g_CtC[i] = 0.f;
    if (i < BS*DD*RR) g_numB[i] = 0.f;
}

// ---------------- shared GEMM core: acc += x(^T clamped?) * b, 64n x 64r, K=512 ----------------
template<bool CLAMPX>
__device__ __forceinline__ void gemmA(const float* __restrict__ x, const float* __restrict__ b,
                                      int bs, int n0, float acc[4][4],
                                      float (*xs)[64], float (*bsm)[64])
{
    int tid = threadIdx.x;
    int tr = tid & 15, tn = tid >> 4;
    int li = tid >> 4, lj = (tid & 15)*4;
    const float* xb = x + (size_t)bs*DD*NN + n0;
    const float* bb = b + bs*DD*RR;
    for (int kc = 0; kc < DD; kc += 16){
        float4 xv = *(const float4*)(xb + (size_t)(kc+li)*NN + lj);
        if (CLAMPX){
            xv.x=fmaxf(xv.x,EPSF); xv.y=fmaxf(xv.y,EPSF);
            xv.z=fmaxf(xv.z,EPSF); xv.w=fmaxf(xv.w,EPSF);
        }
        float4 bv = *(const float4*)(bb + (kc+li)*RR + lj);
        __syncthreads();
        *(float4*)&xs[li][lj]  = xv;
        *(float4*)&bsm[li][lj] = bv;
        __syncthreads();
        #pragma unroll
        for (int k = 0; k < 16; k++){
            float4 xr = *(const float4*)&xs[k][tn*4];
            float4 br = *(const float4*)&bsm[k][tr*4];
            float xa[4] = {xr.x,xr.y,xr.z,xr.w};
            float ba[4] = {br.x,br.y,br.z,br.w};
            #pragma unroll
            for (int a = 0; a < 4; a++)
                #pragma unroll
                for (int c = 0; c < 4; c++)
                    acc[a][c] = fmaf(xa[a], ba[c], acc[a][c]);
        }
    }
}

// MODE: 0 = init coef (softmax, unclamped x), 1 = MU c-step (+CtC), 2 = final c_new
template<int MODE>
__global__ void __launch_bounds__(256) k_cupdate(const float* __restrict__ x, int sel, int clampc){
    __shared__ float xs[16][64];
    __shared__ float bsm[16][64];
    __shared__ float BtBs[RR*RR];
    __shared__ float cs[64][68];
    int bs = blockIdx.y, n0 = blockIdx.x*64;
    int tid = threadIdx.x, tr = tid & 15, tn = tid >> 4;
    float* cb = g_c + ((size_t)bs*NN + n0)*RR;

    if (MODE != 0){
        for (int i = tid; i < RR*RR; i += 256) BtBs[i] = g_BtB[bs*RR*RR + i];
        for (int i = tid; i < 64*64; i += 256){
            int n = i >> 6, r = i & 63;
            float v = cb[n*RR + r];
            cs[n][r] = clampc ? fmaxf(v, EPSF) : v;
        }
        // gemmA's first __syncthreads orders these fills before any reads
    }

    float acc[4][4] = {};
    gemmA<(MODE!=0)>(x, bsel(sel), bs, n0, acc, xs, bsm);

    if (MODE == 0){
        // softmax over r (R=64) per n-row
        #pragma unroll
        for (int a = 0; a < 4; a++){
            float m = fmaxf(fmaxf(acc[a][0],acc[a][1]), fmaxf(acc[a][2],acc[a][3]));
            #pragma unroll
            for (int o = 1; o < 16; o <<= 1) m = fmaxf(m, __shfl_xor_sync(0xffffffffu, m, o));
            float e0 = __expf(acc[a][0]-m), e1 = __expf(acc[a][1]-m);
            float e2 = __expf(acc[a][2]-m), e3 = __expf(acc[a][3]-m);
            float s = e0+e1+e2+e3;
            #pragma unroll
            for (int o = 1; o < 16; o <<= 1) s += __shfl_xor_sync(0xffffffffu, s, o);
            float inv = 1.f / s;
            *(float4*)(cb + (tn*4+a)*RR + tr*4) = make_float4(e0*inv, e1*inv, e2*inv, e3*inv);
        }
        return;
    }

    // denC = c . BtB
    float den[4][4] = {};
    #pragma unroll 4
    for (int s = 0; s < RR; s++){
        float4 bt = *(const float4*)&BtBs[s*RR + tr*4];
        float cv[4];
        #pragma unroll
        for (int a = 0; a < 4; a++) cv[a] = cs[tn*4+a][s];
        #pragma unroll
        for (int a = 0; a < 4; a++){
            den[a][0] = fmaf(cv[a], bt.x, den[a][0]);
            den[a][1] = fmaf(cv[a], bt.y, den[a][1]);
            den[a][2] = fmaf(cv[a], bt.z, den[a][2]);
            den[a][3] = fmaf(cv[a], bt.w, den[a][3]);
        }
    }
    float cnew[4][4];
    #pragma unroll
    for (int a = 0; a < 4; a++)
        #pragma unroll
        for (int c = 0; c < 4; c++)
            cnew[a][c] = cs[tn*4+a][tr*4+c] * acc[a][c] / (den[a][c] + EPSF);

    __syncthreads();   // all cs reads for denC done
    #pragma unroll
    for (int a = 0; a < 4; a++){
        float4 w = make_float4(cnew[a][0], cnew[a][1], cnew[a][2], cnew[a][3]);
        *(float4*)(cb + (tn*4+a)*RR + tr*4) = w;   // store UNCLAMPED c'
        if (MODE == 1) *(float4*)&cs[tn*4+a][tr*4] = w;
    }
    if (MODE == 2) return;
    __syncthreads();

    // CtC partial over this 64-n tile: rows r = tr*4.., cols s = tn*4..
    float ct[4][4] = {};
    #pragma unroll 4
    for (int n = 0; n < 64; n++){
        float4 cr  = *(const float4*)&cs[n][tr*4];
        float4 csv = *(const float4*)&cs[n][tn*4];
        float a_[4] = {cr.x,cr.y,cr.z,cr.w};
        float b_[4] = {csv.x,csv.y,csv.z,csv.w};
        #pragma unroll
        for (int i = 0; i < 4; i++)
            #pragma unroll
            for (int j = 0; j < 4; j++)
                ct[i][j] = fmaf(a_[i], b_[j], ct[i][j]);
    }
    float* ctc = g_CtC + bs*RR*RR;
    #pragma unroll
    for (int i = 0; i < 4; i++)
        #pragma unroll
        for (int j = 0; j < 4; j++)
            atomicAdd(&ctc[(tr*4+i)*RR + tn*4+j], ct[i][j]);
}

// ---------------- numB = clamp(x) . c'  (split-K over N, atomic combine) ----------------
__global__ void __launch_bounds__(256) k_numB(const float* __restrict__ x){
    __shared__ float xs[16][132];   // [n][d], padded, float4-aligned rows
    __shared__ float cs[16][64];
    int bs = blockIdx.z;
    int d0 = blockIdx.y * 128;
    int nbase = blockIdx.x * 2048;
    int tid = threadIdx.x;
    int dl = tid >> 1, nc = (tid & 1) * 8;
    int rq = tid & 15, dg = tid >> 4;
    const float* xb = x + (size_t)bs*DD*NN;
    const float* cbase = g_c + (size_t)bs*NN*RR;
    float acc[8][4] = {};
    for (int nt = nbase; nt < nbase + 2048; nt += 16){
        float4 v0 = *(const float4*)(xb + (size_t)(d0+dl)*NN + nt + nc);
        float4 v1 = *(const float4*)(xb + (size_t)(d0+dl)*NN + nt + nc + 4);
        float4 cv = *(const float4*)(cbase + (size_t)(nt + (tid>>4))*RR + (tid&15)*4);
        __syncthreads();
        xs[nc+0][dl] = fmaxf(v0.x,EPSF); xs[nc+1][dl] = fmaxf(v0.y,EPSF);
        xs[nc+2][dl] = fmaxf(v0.z,EPSF); xs[nc+3][dl] = fmaxf(v0.w,EPSF);
        xs[nc+4][dl] = fmaxf(v1.x,EPSF); xs[nc+5][dl] = fmaxf(v1.y,EPSF);
        xs[nc+6][dl] = fmaxf(v1.z,EPSF); xs[nc+7][dl] = fmaxf(v1.w,EPSF);
        *(float4*)&cs[tid>>4][(tid&15)*4] = cv;
        __syncthreads();
        #pragma unroll
        for (int n = 0; n < 16; n++){
            float4 c4 = *(const float4*)&cs[n][rq*4];
            float4 x0 = *(const float4*)&xs[n][dg*8];
            float4 x1 = *(const float4*)&xs[n][dg*8+4];
            float xa[8] = {x0.x,x0.y,x0.z,x0.w,x1.x,x1.y,x1.z,x1.w};
            float ca[4] = {c4.x,c4.y,c4.z,c4.w};
            #pragma unroll
            for (int i = 0; i < 8; i++)
                #pragma unroll
                for (int j = 0; j < 4; j++)
                    acc[i][j] = fmaf(xa[i], ca[j], acc[i][j]);
        }
    }
    float* nb = g_numB + bs*DD*RR;
    #pragma unroll
    for (int i = 0; i < 8; i++)
        #pragma unroll
        for (int j = 0; j < 4; j++)
            atomicAdd(&nb[(d0 + dg*8 + i)*RR + rq*4 + j], acc[i][j]);
}

// ---------------- b update: denB, multiply, clamp, L2-normalize ----------------
__global__ void __launch_bounds__(128) k_bupdate(int selIn, int selOut){
    int r = blockIdx.x, bs = blockIdx.y;
    int tid = threadIdx.x;
    __shared__ float ctcCol[64];
    __shared__ float red[128];
    const float* bin  = bsel(selIn)  + bs*DD*RR;
    float*       bout = bsel(selOut) + bs*DD*RR;
    const float* nb   = g_numB + bs*DD*RR;
    if (tid < 64) ctcCol[tid] = g_CtC[bs*RR*RR + tid*RR + r];
    __syncthreads();
    float v[4], ss = 0.f;
    #pragma unroll
    for (int q = 0; q < 4; q++){
        int d = tid + q*128;
        const float* brow = bin + d*RR;
        float den = EPSF;
        #pragma unroll 8
        for (int s = 0; s < RR; s++) den = fmaf(brow[s], ctcCol[s], den);
        float t = fmaxf(brow[r] * nb[d*RR + r] / den, EPSF);
        v[q] = t; ss += t*t;
    }
    red[tid] = ss; __syncthreads();
    for (int o = 64; o > 0; o >>= 1){ if (tid < o) red[tid] += red[tid+o]; __syncthreads(); }
    float inv = 1.f / fmaxf(sqrtf(red[0]), 1e-12f);
    #pragma unroll
    for (int q = 0; q < 4; q++)
        bout[(tid + q*128)*RR + r] = v[q] * inv;
}

// ---------------- x_hat = b @ c_new^T ----------------
__global__ void __launch_bounds__(256) k_xhat(float* __restrict__ out, int sel){
    __shared__ float bt[64][68];   // [r][d]
    __shared__ float ct2[64][68];  // [r][n]
    int bs = blockIdx.z;
    int d0 = blockIdx.y * 64;
    int n0 = blockIdx.x * 64;
    int tid = threadIdx.x;
    const float* bb = bsel(sel) + bs*DD*RR;
    const float* cb = g_c + (size_t)bs*NN*RR;
    int rq = tid & 15, gi = tid >> 4;
    #pragma unroll
    for (int it = 0; it < 4; it++){
        int d = gi + it*16;
        float4 bv = *(const float4*)(bb + (d0+d)*RR + rq*4);
        bt[rq*4+0][d] = bv.x; bt[rq*4+1][d] = bv.y; bt[rq*4+2][d] = bv.z; bt[rq*4+3][d] = bv.w;
        int n = gi + it*16;
        float4 cv = *(const float4*)(cb + (size_t)(n0+n)*RR + rq*4);
        ct2[rq*4+0][n] = cv.x; ct2[rq*4+1][n] = cv.y; ct2[rq*4+2][n] = cv.z; ct2[rq*4+3][n] = cv.w;
    }
    __syncthreads();
    int dq = tid >> 4, nq = tid & 15;
    float acc[4][4] = {};
    #pragma unroll 8
    for (int r = 0; r < RR; r++){
        float4 bv = *(const float4*)&bt[r][dq*4];
        float4 cv = *(const float4*)&ct2[r][nq*4];
        float ba[4] = {bv.x,bv.y,bv.z,bv.w};
        float ca[4] = {cv.x,cv.y,cv.z,cv.w};
        #pragma unroll
        for (int i = 0; i < 4; i++)
            #pragma unroll
            for (int j = 0; j < 4; j++)
                acc[i][j] = fmaf(ba[i], ca[j], acc[i][j]);
    }
    #pragma unroll
    for (int i = 0; i < 4; i++)
        *(float4*)(out + (size_t)(bs*DD + d0 + dq*4 + i)*NN + n0 + nq*4) =
            make_float4(acc[i][0], acc[i][1], acc[i][2], acc[i][3]);
}

// ---------------- orchestration ----------------
extern "C" void kernel_launch(void* const* d_in, const int* in_sizes, int n_in,
                              void* d_out, int out_size){
    const float* x     = (const float*)d_in[0];
    const float* bases = (const float*)d_in[1];
    float* out = (float*)d_out;

    k_normb<<<BS*RR, 128>>>(bases);
    int sel = 0;

    // coef init: softmax(x^T b), unclamped x
    k_cupdate<0><<<dim3(NN/64, BS), 256>>>(x, sel, 0);

    for (int step = 0; step < 6; step++){
        int clampc = (step > 0) ? 1 : 0;
        k_btb<<<dim3(16, BS), 256>>>(sel);
        k_zero<<<288, 256>>>();
        k_cupdate<1><<<dim3(NN/64, BS), 256>>>(x, sel, clampc);
        k_numB<<<dim3(32, DD/128, BS), 256>>>(x);
        k_bupdate<<<dim3(RR, BS), 128>>>(sel, 1 - sel);
        sel = 1 - sel;
    }

    // final: c_new = coef * numC/denC, then x_hat = b @ c_new^T
    k_btb<<<dim3(16, BS), 256>>>(sel);
    k_cupdate<2><<<dim3(NN/64, BS), 256>>>(x, sel, 1);
    k_xhat<<<dim3(NN/64, DD/64, BS), 256>>>(out, sel);
}

// round 5
// speedup vs baseline: 1.0798x; 1.0775x over previous
#include <cuda_runtime.h>
#include <cuda_bf16.h>
#include <mma.h>
#include <cstdint>
#include <math.h>
using namespace nvcuda;

#define BS 2
#define DD 512
#define NN 65536
#define RR 64
#define EPSF 1e-6f

// ---------- device scratch (no allocations) ----------
__device__ __align__(16) __nv_bfloat16 g_xtu_h[(size_t)BS*NN*DD], g_xtu_l[(size_t)BS*NN*DD]; // x^T unclamped [n][d]
__device__ __align__(16) __nv_bfloat16 g_xtc_h[(size_t)BS*NN*DD], g_xtc_l[(size_t)BS*NN*DD]; // x^T clamped
__device__ __align__(16) __nv_bfloat16 g_xc_h [(size_t)BS*DD*NN], g_xc_l [(size_t)BS*DD*NN]; // x clamped [d][n]
__device__ __align__(16) __nv_bfloat16 g_ct_h[(size_t)BS*RR*NN], g_ct_l[(size_t)BS*RR*NN];   // c'^T [r][n]
__device__ __align__(16) __nv_bfloat16 g_cn_h[(size_t)BS*NN*RR], g_cn_l[(size_t)BS*NN*RR];   // c_new [n][r]
__device__ __align__(16) __nv_bfloat16 g_bt_h[BS*RR*DD], g_bt_l[BS*RR*DD];                   // b^T [r][d]
__device__ __align__(16) __nv_bfloat16 g_bn_h[BS*DD*RR], g_bn_l[BS*DD*RR];                   // b [d][r]
__device__ __align__(16) float g_c[(size_t)BS*NN*RR];
__device__ float g_b0[BS*DD*RR], g_b1[BS*DD*RR];
__device__ float g_BtB[BS*RR*RR], g_CtC[BS*RR*RR], g_numB[BS*DD*RR];
__device__ __forceinline__ float* bsel(int s){ return s ? g_b1 : g_b0; }

__device__ __forceinline__ void split2(float v, unsigned short& h, unsigned short& l){
    __nv_bfloat16 hb = __float2bfloat16_rn(v);
    __nv_bfloat16 lb = __float2bfloat16_rn(v - __bfloat162float(hb));
    h = __bfloat16_as_ushort(hb); l = __bfloat16_as_ushort(lb);
}
__device__ __forceinline__ uint32_t pk(unsigned short a, unsigned short b){ return (uint32_t)a | ((uint32_t)b << 16); }

// ---------- smem layout (dynamic, 88576 bytes) ----------
// 0      .. 18432  As_h  (128 x 72 bf16)      | overlay after MMA: Ct float[128][72] (0..36864)
// 18432  .. 36864  As_l
// 36864  .. 46080  Bs_h  (64 x 72 bf16)       | overlay after MMA: BtB float[64][64] (36864..53248)
// 46080  .. 55296  Bs_l
// 55296  .. 88576  cold  float[128][65]
#define SMEMG 88576

typedef wmma::fragment<wmma::accumulator,16,16,16,float> AccFrag;

// block GEMM: C[128 x 64] = A[128 x K] * B[K x 64], A rows contiguous (lda), B given
// transposed as Bt[64 x K] rows contiguous (ldb). hi/lo split, 3 products, fp32 acc.
__device__ __forceinline__ void gemm_core(
    const __nv_bfloat16* __restrict__ Ah, const __nv_bfloat16* __restrict__ Al, size_t lda,
    const __nv_bfloat16* __restrict__ Bh, const __nv_bfloat16* __restrict__ Bl, size_t ldb,
    int kchunks, char* sm, AccFrag (&acc)[2][2])
{
    __nv_bfloat16* As_h = (__nv_bfloat16*)(sm);
    __nv_bfloat16* As_l = (__nv_bfloat16*)(sm + 18432);
    __nv_bfloat16* Bs_h = (__nv_bfloat16*)(sm + 36864);
    __nv_bfloat16* Bs_l = (__nv_bfloat16*)(sm + 46080);
    int tid = threadIdx.x;
    int wid = tid >> 5, wm = wid >> 1, wn = wid & 1;
    #pragma unroll
    for (int i = 0; i < 2; i++)
        #pragma unroll
        for (int j = 0; j < 2; j++)
            wmma::fill_fragment(acc[i][j], 0.0f);
    for (int kc = 0; kc < kchunks; kc++){
        __syncthreads();
        size_t k0 = (size_t)kc*64;
        for (int i = tid; i < 1024; i += 256){
            int r = i >> 3, g = (i & 7)*8;
            *(uint4*)(As_h + r*72 + g) = *(const uint4*)(Ah + (size_t)r*lda + k0 + g);
            *(uint4*)(As_l + r*72 + g) = *(const uint4*)(Al + (size_t)r*lda + k0 + g);
        }
        for (int i = tid; i < 512; i += 256){
            int r = i >> 3, g = (i & 7)*8;
            *(uint4*)(Bs_h + r*72 + g) = *(const uint4*)(Bh + (size_t)r*ldb + k0 + g);
            *(uint4*)(Bs_l + r*72 + g) = *(const uint4*)(Bl + (size_t)r*ldb + k0 + g);
        }
        __syncthreads();
        #pragma unroll
        for (int k = 0; k < 4; k++){
            wmma::fragment<wmma::matrix_a,16,16,16,__nv_bfloat16,wmma::row_major> ah[2], al[2];
            wmma::fragment<wmma::matrix_b,16,16,16,__nv_bfloat16,wmma::col_major> bh[2], bl[2];
            #pragma unroll
            for (int i = 0; i < 2; i++){
                wmma::load_matrix_sync(ah[i], As_h + (wm*32+i*16)*72 + k*16, 72);
                wmma::load_matrix_sync(al[i], As_l + (wm*32+i*16)*72 + k*16, 72);
                wmma::load_matrix_sync(bh[i], Bs_h + (wn*32+i*16)*72 + k*16, 72);
                wmma::load_matrix_sync(bl[i], Bs_l + (wn*32+i*16)*72 + k*16, 72);
            }
            #pragma unroll
            for (int i = 0; i < 2; i++)
                #pragma unroll
                for (int j = 0; j < 2; j++){
                    wmma::mma_sync(acc[i][j], ah[i], bh[j], acc[i][j]);
                    wmma::mma_sync(acc[i][j], ah[i], bl[j], acc[i][j]);
                    wmma::mma_sync(acc[i][j], al[i], bh[j], acc[i][j]);
                }
        }
    }
    __syncthreads();   // done reading As/Bs; overlays may now be written
}

__device__ __forceinline__ void store_acc(char* sm, AccFrag (&acc)[2][2]){
    float* Ct = (float*)sm;
    int wid = threadIdx.x >> 5, wm = wid >> 1, wn = wid & 1;
    #pragma unroll
    for (int i = 0; i < 2; i++)
        #pragma unroll
        for (int j = 0; j < 2; j++)
            wmma::store_matrix_sync(Ct + (wm*32+i*16)*72 + wn*32+j*16, acc[i][j], 72, wmma::mem_row_major);
}

// ---------- prep: bf16 splits of x ----------
__global__ void __launch_bounds__(256) k_prep(const float* __restrict__ x){
    __shared__ float su[64][65], sc[64][65];
    int bs = blockIdx.z, d0 = blockIdx.y*64, n0 = blockIdx.x*64, tid = threadIdx.x;
    #pragma unroll
    for (int q = 0; q < 4; q++){
        int idx = q*256 + tid, d = idx >> 4, n4 = (idx & 15)*4;
        float4 v = *(const float4*)(x + ((size_t)bs*DD + d0+d)*NN + n0 + n4);
        float4 c = make_float4(fmaxf(v.x,EPSF), fmaxf(v.y,EPSF), fmaxf(v.z,EPSF), fmaxf(v.w,EPSF));
        unsigned short h[4], l[4];
        split2(c.x,h[0],l[0]); split2(c.y,h[1],l[1]); split2(c.z,h[2],l[2]); split2(c.w,h[3],l[3]);
        size_t oc = ((size_t)bs*DD + d0+d)*NN + n0 + n4;
        *(uint2*)(g_xc_h + oc) = make_uint2(pk(h[0],h[1]), pk(h[2],h[3]));
        *(uint2*)(g_xc_l + oc) = make_uint2(pk(l[0],l[1]), pk(l[2],l[3]));
        su[d][n4]=v.x; su[d][n4+1]=v.y; su[d][n4+2]=v.z; su[d][n4+3]=v.w;
        sc[d][n4]=c.x; sc[d][n4+1]=c.y; sc[d][n4+2]=c.z; sc[d][n4+3]=c.w;
    }
    __syncthreads();
    #pragma unroll
    for (int q = 0; q < 4; q++){
        int idx = q*256 + tid, n = idx >> 4, d4 = (idx & 15)*4;
        size_t ot = ((size_t)bs*NN + n0+n)*DD + d0 + d4;
        unsigned short h[4], l[4];
        #pragma unroll
        for (int i = 0; i < 4; i++) split2(su[d4+i][n], h[i], l[i]);
        *(uint2*)(g_xtu_h + ot) = make_uint2(pk(h[0],h[1]), pk(h[2],h[3]));
        *(uint2*)(g_xtu_l + ot) = make_uint2(pk(l[0],l[1]), pk(l[2],l[3]));
        #pragma unroll
        for (int i = 0; i < 4; i++) split2(sc[d4+i][n], h[i], l[i]);
        *(uint2*)(g_xtc_h + ot) = make_uint2(pk(h[0],h[1]), pk(h[2],h[3]));
        *(uint2*)(g_xtc_l + ot) = make_uint2(pk(l[0],l[1]), pk(l[2],l[3]));
    }
}

// ---------- normalize bases; write fp32 b0 + b^T splits ----------
__global__ void __launch_bounds__(128) k_normb(const float* __restrict__ bases){
    int bs = blockIdx.x >> 6, r = blockIdx.x & 63, tid = threadIdx.x;
    __shared__ float red[128];
    float s = 0.f;
    for (int d = tid; d < DD; d += 128){ float v = bases[(bs*DD+d)*RR + r]; s += v*v; }
    red[tid] = s; __syncthreads();
    for (int o = 64; o > 0; o >>= 1){ if (tid < o) red[tid] += red[tid+o]; __syncthreads(); }
    float inv = 1.f / fmaxf(sqrtf(red[0]), 1e-12f);
    for (int d = tid; d < DD; d += 128){
        float v = bases[(bs*DD+d)*RR + r] * inv;
        g_b0[(bs*DD+d)*RR + r] = v;
        unsigned short h, l; split2(v, h, l);
        g_bt_h[(bs*RR+r)*DD + d] = __ushort_as_bfloat16(h);
        g_bt_l[(bs*RR+r)*DD + d] = __ushort_as_bfloat16(l);
    }
}

__global__ void __launch_bounds__(256) k_btb(int sel){
    const float* bb = bsel(sel) + blockIdx.y*DD*RR;
    int p = blockIdx.x*256 + threadIdx.x, r = p & 63, s = p >> 6;
    float acc = 0.f;
    for (int d = 0; d < DD; d++) acc = fmaf(bb[d*RR+r], bb[d*RR+s], acc);
    g_BtB[blockIdx.y*RR*RR + p] = acc;
}
__global__ void k_zero(){
    int i = blockIdx.x*256 + threadIdx.x;
    if (i < BS*RR*RR) g_CtC[i] = 0.f;
    if (i < BS*DD*RR) g_numB[i] = 0.f;
}

// ---------- fused c kernel: numC + epilogue. MODE 0=init softmax, 1=MU step, 2=final ----------
template<int MODE>
__global__ void __launch_bounds__(256) k_cmma(int clampc){
    extern __shared__ char sm[];
    int bs = blockIdx.y, n0 = blockIdx.x*128, tid = threadIdx.x;
    const __nv_bfloat16* xh = (MODE==0 ? g_xtu_h : g_xtc_h) + ((size_t)bs*NN + n0)*DD;
    const __nv_bfloat16* xl = (MODE==0 ? g_xtu_l : g_xtc_l) + ((size_t)bs*NN + n0)*DD;
    float* csm = (float*)(sm + 55296);  // [128][65] clamped old c

    if (MODE != 0){
        size_t cbase = ((size_t)bs*NN + n0)*RR;
        for (int i = tid; i < 2048; i += 256){
            int n = i >> 4, r4 = (i & 15)*4;
            float4 v = *(const float4*)(g_c + cbase + n*RR + r4);
            if (clampc){ v.x=fmaxf(v.x,EPSF); v.y=fmaxf(v.y,EPSF); v.z=fmaxf(v.z,EPSF); v.w=fmaxf(v.w,EPSF); }
            csm[n*65+r4]=v.x; csm[n*65+r4+1]=v.y; csm[n*65+r4+2]=v.z; csm[n*65+r4+3]=v.w;
        }
    }

    AccFrag acc[2][2];
    gemm_core(xh, xl, DD, g_bt_h + bs*RR*DD, g_bt_l + bs*RR*DD, DD, DD/64, sm, acc);
    store_acc(sm, acc);
    float* Ct = (float*)sm;
    float* Bt = (float*)(sm + 36864);
    if (MODE != 0)
        for (int i = tid; i < RR*RR; i += 256) Bt[i] = g_BtB[bs*RR*RR + i];
    __syncthreads();

    int n = tid >> 1, h = tid & 1;
    size_t crow = ((size_t)bs*NN + n0 + n)*RR;

    if (MODE == 0){
        float v[32], m = -1e30f;
        #pragma unroll
        for (int j = 0; j < 32; j++){ v[j] = Ct[n*72 + h*32 + j]; m = fmaxf(m, v[j]); }
        m = fmaxf(m, __shfl_xor_sync(0xffffffffu, m, 1));
        float s = 0.f;
        #pragma unroll
        for (int j = 0; j < 32; j++){ v[j] = __expf(v[j]-m); s += v[j]; }
        s += __shfl_xor_sync(0xffffffffu, s, 1);
        float inv = 1.f/s;
        #pragma unroll
        for (int j4 = 0; j4 < 32; j4 += 4)
            *(float4*)(g_c + crow + h*32 + j4) = make_float4(v[j4]*inv, v[j4+1]*inv, v[j4+2]*inv, v[j4+3]*inv);
        return;
    }

    float den[32];
    #pragma unroll
    for (int j = 0; j < 32; j++) den[j] = 0.f;
    #pragma unroll 8
    for (int s = 0; s < 64; s++){
        float cv = csm[n*65 + s];
        const float* row = &Bt[s*64 + h*32];
        #pragma unroll
        for (int j = 0; j < 32; j++) den[j] = fmaf(cv, row[j], den[j]);
    }
    #pragma unroll
    for (int j4 = 0; j4 < 32; j4 += 4){
        float cp[4];
        #pragma unroll
        for (int t = 0; t < 4; t++){
            int j = j4 + t;
            float cold = csm[n*65 + h*32 + j];
            cp[t] = cold * Ct[n*72 + h*32 + j] / (den[j] + EPSF);
            Ct[n*72 + h*32 + j] = cp[t];   // own cells, in-place
        }
        if (MODE == 1)
            *(float4*)(g_c + crow + h*32 + j4) = make_float4(cp[0], cp[1], cp[2], cp[3]);
        else {
            unsigned short hh[4], ll[4];
            #pragma unroll
            for (int t = 0; t < 4; t++) split2(cp[t], hh[t], ll[t]);
            size_t o = crow + h*32 + j4;
            *(uint2*)(g_cn_h + o) = make_uint2(pk(hh[0],hh[1]), pk(hh[2],hh[3]));
            *(uint2*)(g_cn_l + o) = make_uint2(pk(ll[0],ll[1]), pk(ll[2],ll[3]));
        }
    }
    if (MODE == 2) return;
    __syncthreads();

    // transpose c' -> g_ct splits, and CtC partial (Ct now holds c')
    int r = tid & 63, q = tid >> 6;
    for (int i4 = 0; i4 < 32; i4 += 4){
        unsigned short hh[4], ll[4];
        #pragma unroll
        for (int t = 0; t < 4; t++) split2(Ct[(q*32 + i4 + t)*72 + r], hh[t], ll[t]);
        size_t o = ((size_t)bs*RR + r)*NN + n0 + q*32 + i4;
        *(uint2*)(g_ct_h + o) = make_uint2(pk(hh[0],hh[1]), pk(hh[2],hh[3]));
        *(uint2*)(g_ct_l + o) = make_uint2(pk(ll[0],ll[1]), pk(ll[2],ll[3]));
    }
    float ctc[16];
    #pragma unroll
    for (int j = 0; j < 16; j++) ctc[j] = 0.f;
    for (int nn2 = 0; nn2 < 128; nn2++){
        float cr = Ct[nn2*72 + r];
        const float* row = &Ct[nn2*72 + q*16];
        #pragma unroll
        for (int j = 0; j < 16; j++) ctc[j] = fmaf(cr, row[j], ctc[j]);
    }
    float* gout = g_CtC + bs*RR*RR + r*RR + q*16;
    #pragma unroll
    for (int j = 0; j < 16; j++) atomicAdd(&gout[j], ctc[j]);
}

// ---------- numB = xc . c' (split-K over N, atomic combine) ----------
__global__ void __launch_bounds__(256) k_numBmma(){
    extern __shared__ char sm[];
    int bs = blockIdx.z, d0 = blockIdx.y*128, tid = threadIdx.x;
    size_t nb = (size_t)blockIdx.x * 2048;
    AccFrag acc[2][2];
    gemm_core(g_xc_h + ((size_t)bs*DD + d0)*NN + nb, g_xc_l + ((size_t)bs*DD + d0)*NN + nb, NN,
              g_ct_h + (size_t)bs*RR*NN + nb,        g_ct_l + (size_t)bs*RR*NN + nb,        NN,
              2048/64, sm, acc);
    store_acc(sm, acc);
    __syncthreads();
    float* Ct = (float*)sm;
    int d = tid >> 1, h = tid & 1;
    float* out = g_numB + (bs*DD + d0 + d)*RR + h*32;
    #pragma unroll
    for (int j = 0; j < 32; j++) atomicAdd(&out[j], Ct[d*72 + h*32 + j]);
}

// ---------- b update (exact fp32) + split writes ----------
__global__ void __launch_bounds__(128) k_bupdate(int selIn, int selOut){
    int r = blockIdx.x, bs = blockIdx.y, tid = threadIdx.x;
    __shared__ float ctcCol[64], red[128];
    const float* bin = bsel(selIn) + bs*DD*RR;
    float* bout = bsel(selOut) + bs*DD*RR;
    const float* nb = g_numB + bs*DD*RR;
    if (tid < 64) ctcCol[tid] = g_CtC[bs*RR*RR + tid*RR + r];
    __syncthreads();
    float v[4], ss = 0.f;
    #pragma unroll
    for (int q = 0; q < 4; q++){
        int d = tid + q*128; const float* brow = bin + d*RR;
        float den = EPSF;
        #pragma unroll 8
        for (int s = 0; s < RR; s++) den = fmaf(brow[s], ctcCol[s], den);
        float t = fmaxf(brow[r] * nb[d*RR + r] / den, EPSF);
        v[q] = t; ss += t*t;
    }
    red[tid] = ss; __syncthreads();
    for (int o = 64; o > 0; o >>= 1){ if (tid < o) red[tid] += red[tid+o]; __syncthreads(); }
    float inv = 1.f / fmaxf(sqrtf(red[0]), 1e-12f);
    #pragma unroll
    for (int q = 0; q < 4; q++){
        int d = tid + q*128;
        float w = v[q] * inv;
        bout[d*RR + r] = w;
        unsigned short h, l; split2(w, h, l);
        g_bt_h[(bs*RR+r)*DD + d] = __ushort_as_bfloat16(h);
        g_bt_l[(bs*RR+r)*DD + d] = __ushort_as_bfloat16(l);
        g_bn_h[(bs*DD+d)*RR + r] = __ushort_as_bfloat16(h);
        g_bn_l[(bs*DD+d)*RR + r] = __ushort_as_bfloat16(l);
    }
}

// ---------- x_hat = b @ c_new^T ----------
__global__ void __launch_bounds__(256) k_xhat(float* __restrict__ out){
    extern __shared__ char sm[];
    int bs = blockIdx.z, d0 = blockIdx.y*128, n0 = blockIdx.x*64, tid = threadIdx.x;
    AccFrag acc[2][2];
    gemm_core(g_bn_h + (bs*DD + d0)*RR,             g_bn_l + (bs*DD + d0)*RR,             RR,
              g_cn_h + ((size_t)bs*NN + n0)*RR,     g_cn_l + ((size_t)bs*NN + n0)*RR,     RR,
              1, sm, acc);
    store_acc(sm, acc);
    __syncthreads();
    float* Ct = (float*)sm;
    int d = tid >> 1, h = tid & 1;
    float* orow = out + (size_t)(bs*DD + d0 + d)*NN + n0 + h*32;
    #pragma unroll
    for (int j4 = 0; j4 < 32; j4 += 4)
        *(float4*)(orow + j4) = make_float4(Ct[d*72+h*32+j4], Ct[d*72+h*32+j4+1], Ct[d*72+h*32+j4+2], Ct[d*72+h*32+j4+3]);
}

// ---------- orchestration ----------
extern "C" void kernel_launch(void* const* d_in, const int* in_sizes, int n_in,
                              void* d_out, int out_size){
    const float* x = (const float*)d_in[0];
    const float* bases = (const float*)d_in[1];
    float* out = (float*)d_out;

    cudaFuncSetAttribute(k_cmma<0>, cudaFuncAttributeMaxDynamicSharedMemorySize, SMEMG);
    cudaFuncSetAttribute(k_cmma<1>, cudaFuncAttributeMaxDynamicSharedMemorySize, SMEMG);
    cudaFuncSetAttribute(k_cmma<2>, cudaFuncAttributeMaxDynamicSharedMemorySize, SMEMG);
    cudaFuncSetAttribute(k_numBmma, cudaFuncAttributeMaxDynamicSharedMemorySize, SMEMG);
    cudaFuncSetAttribute(k_xhat,    cudaFuncAttributeMaxDynamicSharedMemorySize, SMEMG);

    k_prep<<<dim3(NN/64, DD/64, BS), 256>>>(x);
    k_normb<<<BS*RR, 128>>>(bases);
    int sel = 0;
    k_cmma<0><<<dim3(NN/128, BS), 256, SMEMG>>>(0);
    for (int step = 0; step < 6; step++){
        k_btb<<<dim3(16, BS), 256>>>(sel);
        k_zero<<<256, 256>>>();
        k_cmma<1><<<dim3(NN/128, BS), 256, SMEMG>>>(step > 0 ? 1 : 0);
        k_numBmma<<<dim3(32, DD/128, BS), 256, SMEMG>>>();
        k_bupdate<<<dim3(RR, BS), 128>>>(sel, 1 - sel);
        sel = 1 - sel;
    }
    k_btb<<<dim3(16, BS), 256>>>(sel);
    k_cmma<2><<<dim3(NN/128, BS), 256, SMEMG>>>(1);
    k_xhat<<<dim3(NN/64, DD/128, BS), 256, SMEMG>>>(out);
}

// round 6
// speedup vs baseline: 1.4060x; 1.3021x over previous
#include <cuda_runtime.h>
#include <cuda_bf16.h>
#include <mma.h>
#include <cstdint>
#include <math.h>
using namespace nvcuda;
typedef __nv_bfloat16 bf16;

#define BS 2
#define DD 512
#define NN 65536
#define RR 64
#define EPSF 1e-6f

// ---------- device scratch ----------
__device__ __align__(16) bf16 g_xu_h[(size_t)BS*DD*NN], g_xu_l[(size_t)BS*DD*NN]; // x unclamped [d][n]
__device__ __align__(16) bf16 g_xc_h[(size_t)BS*DD*NN], g_xc_l[(size_t)BS*DD*NN]; // x clamped   [d][n]
__device__ __align__(16) bf16 g_ct_h[(size_t)BS*RR*NN], g_ct_l[(size_t)BS*RR*NN]; // c'^T [r][n]
__device__ __align__(16) bf16 g_cn_h[(size_t)BS*NN*RR], g_cn_l[(size_t)BS*NN*RR]; // c_new [n][r]
__device__ __align__(16) bf16 g_bt_h[BS*RR*DD], g_bt_l[BS*RR*DD];                 // b^T [r][d]
__device__ __align__(16) bf16 g_bn_h[BS*DD*RR], g_bn_l[BS*DD*RR];                 // b [d][r]
__device__ __align__(16) float g_c[(size_t)BS*NN*RR];
__device__ float g_b0[BS*DD*RR], g_b1[BS*DD*RR];
__device__ float g_BtB[BS*RR*RR], g_CtC[BS*RR*RR], g_numB[BS*DD*RR];
__device__ __forceinline__ float* bsel(int s){ return s ? g_b1 : g_b0; }

__device__ __forceinline__ void split2(float v, unsigned short& h, unsigned short& l){
    bf16 hb = __float2bfloat16_rn(v);
    bf16 lb = __float2bfloat16_rn(v - __bfloat162float(hb));
    h = __bfloat16_as_ushort(hb); l = __bfloat16_as_ushort(lb);
}
__device__ __forceinline__ uint32_t pk(unsigned short a, unsigned short b){ return (uint32_t)a | ((uint32_t)b << 16); }
__device__ __forceinline__ uint32_t smem_u32(const void* p){
    uint32_t a; asm("{ .reg .u64 t; cvta.to.shared.u64 t, %1; cvt.u32.u64 %0, t; }" : "=r"(a) : "l"(p)); return a;
}
__device__ __forceinline__ void cpa16(uint32_t s, const void* g){
    asm volatile("cp.async.cg.shared.global [%0], [%1], 16;" :: "r"(s), "l"(g) : "memory");
}

// ---------- smem: A stages 2x20480 @0, B stages 2x10240 @40960..61440
// overlays after mainloop: Ct f32[128][72] @0 (36864), BtB f32 @40960 (16384)
// csm f32[128][65] @61440 (33280). total 94720.
#define AST(st) ((st)*20480)
#define BST(st) (40960 + (st)*10240)
#define SMEMG 94720

typedef wmma::fragment<wmma::accumulator,16,16,16,float> AccFrag;

template<bool ACOL>
__device__ __forceinline__ void issue_chunk(uint32_t sb, int st,
    const bf16* __restrict__ Ah, const bf16* __restrict__ Al, size_t lda,
    const bf16* __restrict__ Bh, const bf16* __restrict__ Bl, size_t ldb, size_t k0)
{
    int t = threadIdx.x;
    uint32_t ab = sb + AST(st), bb = sb + BST(st);
    if (ACOL){ // 32 k-rows x 128 m, smem stride 136
        #pragma unroll
        for (int u = 0; u < 2; u++){
            int idx = t + u*256, r = idx >> 4, sg = (idx & 15)*8;
            cpa16(ab +        (r*136 + sg)*2, Ah + (k0+r)*lda + sg);
            cpa16(ab + 8704 + (r*136 + sg)*2, Al + (k0+r)*lda + sg);
        }
    } else {   // 128 m-rows x 32 k, smem stride 40
        #pragma unroll
        for (int u = 0; u < 2; u++){
            int idx = t + u*256, r = idx >> 2, sg = (idx & 3)*8;
            cpa16(ab +         (r*40 + sg)*2, Ah + r*lda + k0 + sg);
            cpa16(ab + 10240 + (r*40 + sg)*2, Al + r*lda + k0 + sg);
        }
    }
    { int r = t >> 2, sg = (t & 3)*8; // 64 rows x 32 k, stride 40
      cpa16(bb +        (r*40 + sg)*2, Bh + r*ldb + k0 + sg);
      cpa16(bb + 5120 + (r*40 + sg)*2, Bl + r*ldb + k0 + sg);
    }
    asm volatile("cp.async.commit_group;" ::: "memory");
}

template<bool ACOL>
__device__ __forceinline__ void gemm_core(
    const bf16* __restrict__ Ah, const bf16* __restrict__ Al, size_t lda,
    const bf16* __restrict__ Bh, const bf16* __restrict__ Bl, size_t ldb,
    int kchunks, char* sm, uint32_t sb, AccFrag (&acc)[2][2])
{
    int wid = threadIdx.x >> 5, wm = wid >> 1, wn = wid & 1;
    #pragma unroll
    for (int i = 0; i < 2; i++)
        #pragma unroll
        for (int j = 0; j < 2; j++) wmma::fill_fragment(acc[i][j], 0.0f);
    issue_chunk<ACOL>(sb, 0, Ah, Al, lda, Bh, Bl, ldb, 0);
    for (int kc = 0; kc < kchunks; kc++){
        int cur = kc & 1;
        if (kc + 1 < kchunks){
            issue_chunk<ACOL>(sb, cur^1, Ah, Al, lda, Bh, Bl, ldb, (size_t)(kc+1)*32);
            asm volatile("cp.async.wait_group 1;" ::: "memory");
        } else {
            asm volatile("cp.async.wait_group 0;" ::: "memory");
        }
        __syncthreads();
        bf16* As = (bf16*)(sm + AST(cur));
        bf16* Bs = (bf16*)(sm + BST(cur));
        #pragma unroll
        for (int k = 0; k < 2; k++){
            wmma::fragment<wmma::matrix_b,16,16,16,bf16,wmma::col_major> fbh[2], fbl[2];
            #pragma unroll
            for (int j = 0; j < 2; j++){
                wmma::load_matrix_sync(fbh[j], Bs + (wn*32+j*16)*40 + k*16, 40);
                wmma::load_matrix_sync(fbl[j], Bs + 2560 + (wn*32+j*16)*40 + k*16, 40);
            }
            if (ACOL){
                wmma::fragment<wmma::matrix_a,16,16,16,bf16,wmma::col_major> fah[2], fal[2];
                #pragma unroll
                for (int i = 0; i < 2; i++){
                    wmma::load_matrix_sync(fah[i], As + (k*16)*136 + wm*32+i*16, 136);
                    wmma::load_matrix_sync(fal[i], As + 4352 + (k*16)*136 + wm*32+i*16, 136);
                }
                #pragma unroll
                for (int i = 0; i < 2; i++)
                    #pragma unroll
                    for (int j = 0; j < 2; j++){
                        wmma::mma_sync(acc[i][j], fah[i], fbh[j], acc[i][j]);
                        wmma::mma_sync(acc[i][j], fah[i], fbl[j], acc[i][j]);
                        wmma::mma_sync(acc[i][j], fal[i], fbh[j], acc[i][j]);
                    }
            } else {
                wmma::fragment<wmma::matrix_a,16,16,16,bf16,wmma::row_major> fah[2], fal[2];
                #pragma unroll
                for (int i = 0; i < 2; i++){
                    wmma::load_matrix_sync(fah[i], As + (wm*32+i*16)*40 + k*16, 40);
                    wmma::load_matrix_sync(fal[i], As + 5120 + (wm*32+i*16)*40 + k*16, 40);
                }
                #pragma unroll
                for (int i = 0; i < 2; i++)
                    #pragma unroll
                    for (int j = 0; j < 2; j++){
                        wmma::mma_sync(acc[i][j], fah[i], fbh[j], acc[i][j]);
                        wmma::mma_sync(acc[i][j], fah[i], fbl[j], acc[i][j]);
                        wmma::mma_sync(acc[i][j], fal[i], fbh[j], acc[i][j]);
                    }
            }
        }
        __syncthreads();
    }
}

__device__ __forceinline__ void store_acc(char* sm, AccFrag (&acc)[2][2]){
    float* Ct = (float*)sm;
    int wid = threadIdx.x >> 5, wm = wid >> 1, wn = wid & 1;
    #pragma unroll
    for (int i = 0; i < 2; i++)
        #pragma unroll
        for (int j = 0; j < 2; j++)
            wmma::store_matrix_sync(Ct + (wm*32+i*16)*72 + wn*32+j*16, acc[i][j], 72, wmma::mem_row_major);
}

// ---------- prep: bf16 splits of x (both clamped + unclamped, [d][n]) ----------
__global__ void __launch_bounds__(256) k_prep(const float* __restrict__ x){
    size_t base = ((size_t)blockIdx.x*256 + threadIdx.x)*16;
    #pragma unroll
    for (int q = 0; q < 4; q++){
        size_t o = base + q*4;
        float4 v = *(const float4*)(x + o);
        unsigned short h[4], l[4];
        split2(v.x,h[0],l[0]); split2(v.y,h[1],l[1]); split2(v.z,h[2],l[2]); split2(v.w,h[3],l[3]);
        *(uint2*)(g_xu_h + o) = make_uint2(pk(h[0],h[1]), pk(h[2],h[3]));
        *(uint2*)(g_xu_l + o) = make_uint2(pk(l[0],l[1]), pk(l[2],l[3]));
        split2(fmaxf(v.x,EPSF),h[0],l[0]); split2(fmaxf(v.y,EPSF),h[1],l[1]);
        split2(fmaxf(v.z,EPSF),h[2],l[2]); split2(fmaxf(v.w,EPSF),h[3],l[3]);
        *(uint2*)(g_xc_h + o) = make_uint2(pk(h[0],h[1]), pk(h[2],h[3]));
        *(uint2*)(g_xc_l + o) = make_uint2(pk(l[0],l[1]), pk(l[2],l[3]));
    }
}

__global__ void __launch_bounds__(128) k_normb(const float* __restrict__ bases){
    int bs = blockIdx.x >> 6, r = blockIdx.x & 63, tid = threadIdx.x;
    __shared__ float red[128];
    float s = 0.f;
    for (int d = tid; d < DD; d += 128){ float v = bases[(bs*DD+d)*RR + r]; s += v*v; }
    red[tid] = s; __syncthreads();
    for (int o = 64; o > 0; o >>= 1){ if (tid < o) red[tid] += red[tid+o]; __syncthreads(); }
    float inv = 1.f / fmaxf(sqrtf(red[0]), 1e-12f);
    for (int d = tid; d < DD; d += 128){
        float v = bases[(bs*DD+d)*RR + r] * inv;
        g_b0[(bs*DD+d)*RR + r] = v;
        unsigned short h, l; split2(v, h, l);
        g_bt_h[(bs*RR+r)*DD + d] = __ushort_as_bfloat16(h);
        g_bt_l[(bs*RR+r)*DD + d] = __ushort_as_bfloat16(l);
    }
}

__global__ void k_zero(){
    int i = blockIdx.x*256 + threadIdx.x;
    if (i < BS*RR*RR){ g_BtB[i] = 0.f; g_CtC[i] = 0.f; }
    if (i < BS*DD*RR) g_numB[i] = 0.f;
}

// BtB split-D partials: grid (8, BS); smem staging + atomic combine
__global__ void __launch_bounds__(256) k_btb(int sel){
    __shared__ float bsh[64][65];
    int bs = blockIdx.y, d0 = blockIdx.x*64, tid = threadIdx.x;
    const float* bb = bsel(sel) + bs*DD*RR + d0*RR;
    for (int i = tid*4; i < 4096; i += 1024){
        float4 v = *(const float4*)(bb + i);
        int d = i >> 6, r = i & 63;
        bsh[d][r]=v.x; bsh[d][r+1]=v.y; bsh[d][r+2]=v.z; bsh[d][r+3]=v.w;
    }
    __syncthreads();
    int r = tid & 63, sq = (tid >> 6)*16;
    float acc[16];
    #pragma unroll
    for (int j = 0; j < 16; j++) acc[j] = 0.f;
    for (int d = 0; d < 64; d++){
        float br = bsh[d][r];
        #pragma unroll
        for (int j = 0; j < 16; j++) acc[j] = fmaf(br, bsh[d][sq+j], acc[j]);
    }
    float* o = g_BtB + bs*RR*RR + r*RR + sq;
    #pragma unroll
    for (int j = 0; j < 16; j++) atomicAdd(&o[j], acc[j]);
}

// ---------- fused c kernel ----------
template<int MODE>
__global__ void __launch_bounds__(256) k_cmma(int clampc){
    extern __shared__ char sm[];
    uint32_t sb = smem_u32(sm);
    int bs = blockIdx.y, n0 = blockIdx.x*128, tid = threadIdx.x;
    const bf16* xh = (MODE==0 ? g_xu_h : g_xc_h) + (size_t)bs*DD*NN + n0;
    const bf16* xl = (MODE==0 ? g_xu_l : g_xc_l) + (size_t)bs*DD*NN + n0;
    float* csm = (float*)(sm + 61440);
    if (MODE != 0){
        size_t cbase = ((size_t)bs*NN + n0)*RR;
        for (int i = tid; i < 2048; i += 256){
            int n = i >> 4, r4 = (i & 15)*4;
            float4 v = *(const float4*)(g_c + cbase + n*RR + r4);
            if (clampc){ v.x=fmaxf(v.x,EPSF); v.y=fmaxf(v.y,EPSF); v.z=fmaxf(v.z,EPSF); v.w=fmaxf(v.w,EPSF); }
            csm[n*65+r4]=v.x; csm[n*65+r4+1]=v.y; csm[n*65+r4+2]=v.z; csm[n*65+r4+3]=v.w;
        }
    }
    AccFrag acc[2][2];
    gemm_core<true>(xh, xl, NN, g_bt_h + bs*RR*DD, g_bt_l + bs*RR*DD, DD, 16, sm, sb, acc);
    store_acc(sm, acc);
    float* Ct = (float*)sm;
    float* Bt = (float*)(sm + 40960);
    if (MODE != 0)
        for (int i = tid; i < RR*RR; i += 256) Bt[i] = g_BtB[bs*RR*RR + i];
    __syncthreads();

    int n = tid >> 1, h = tid & 1;
    size_t crow = ((size_t)bs*NN + n0 + n)*RR;
    if (MODE == 0){
        float v[32], m = -1e30f;
        #pragma unroll
        for (int j = 0; j < 32; j++){ v[j] = Ct[n*72 + h*32 + j]; m = fmaxf(m, v[j]); }
        m = fmaxf(m, __shfl_xor_sync(0xffffffffu, m, 1));
        float s = 0.f;
        #pragma unroll
        for (int j = 0; j < 32; j++){ v[j] = __expf(v[j]-m); s += v[j]; }
        s += __shfl_xor_sync(0xffffffffu, s, 1);
        float inv = 1.f/s;
        #pragma unroll
        for (int j4 = 0; j4 < 32; j4 += 4)
            *(float4*)(g_c + crow + h*32 + j4) = make_float4(v[j4]*inv, v[j4+1]*inv, v[j4+2]*inv, v[j4+3]*inv);
        return;
    }
    float den[32];
    #pragma unroll
    for (int j = 0; j < 32; j++) den[j] = 0.f;
    #pragma unroll 8
    for (int s = 0; s < 64; s++){
        float cv = csm[n*65 + s];
        const float* row = &Bt[s*64 + h*32];
        #pragma unroll
        for (int j = 0; j < 32; j++) den[j] = fmaf(cv, row[j], den[j]);
    }
    #pragma unroll
    for (int j4 = 0; j4 < 32; j4 += 4){
        float cp[4];
        #pragma unroll
        for (int t = 0; t < 4; t++){
            int j = j4 + t;
            float cold = csm[n*65 + h*32 + j];
            cp[t] = cold * Ct[n*72 + h*32 + j] / (den[j] + EPSF);
            Ct[n*72 + h*32 + j] = cp[t];
        }
        if (MODE == 1)
            *(float4*)(g_c + crow + h*32 + j4) = make_float4(cp[0], cp[1], cp[2], cp[3]);
        else {
            unsigned short hh[4], ll[4];
            #pragma unroll
            for (int t = 0; t < 4; t++) split2(cp[t], hh[t], ll[t]);
            size_t o = crow + h*32 + j4;
            *(uint2*)(g_cn_h + o) = make_uint2(pk(hh[0],hh[1]), pk(hh[2],hh[3]));
            *(uint2*)(g_cn_l + o) = make_uint2(pk(ll[0],ll[1]), pk(ll[2],ll[3]));
        }
    }
    if (MODE == 2) return;
    __syncthreads();
    int r = tid & 63, q = tid >> 6;
    for (int i4 = 0; i4 < 32; i4 += 4){
        unsigned short hh[4], ll[4];
        #pragma unroll
        for (int t = 0; t < 4; t++) split2(Ct[(q*32 + i4 + t)*72 + r], hh[t], ll[t]);
        size_t o = ((size_t)bs*RR + r)*NN + n0 + q*32 + i4;
        *(uint2*)(g_ct_h + o) = make_uint2(pk(hh[0],hh[1]), pk(hh[2],hh[3]));
        *(uint2*)(g_ct_l + o) = make_uint2(pk(ll[0],ll[1]), pk(ll[2],ll[3]));
    }
    float ctc[16];
    #pragma unroll
    for (int j = 0; j < 16; j++) ctc[j] = 0.f;
    for (int nn2 = 0; nn2 < 128; nn2++){
        float cr = Ct[nn2*72 + r];
        const float* row = &Ct[nn2*72 + (q*16)];
        #pragma unroll
        for (int j = 0; j < 16; j++) ctc[j] = fmaf(cr, row[j], ctc[j]);
    }
    float* gout = g_CtC + bs*RR*RR + r*RR + q*16;
    #pragma unroll
    for (int j = 0; j < 16; j++) atomicAdd(&gout[j], ctc[j]);
}

// ---------- numB ----------
__global__ void __launch_bounds__(256) k_numBmma(){
    extern __shared__ char sm[];
    uint32_t sb = smem_u32(sm);
    int bs = blockIdx.z, d0 = blockIdx.y*128, tid = threadIdx.x;
    size_t nb = (size_t)blockIdx.x * 2048;
    AccFrag acc[2][2];
    gemm_core<false>(g_xc_h + ((size_t)bs*DD + d0)*NN + nb, g_xc_l + ((size_t)bs*DD + d0)*NN + nb, NN,
                     g_ct_h + (size_t)bs*RR*NN + nb,        g_ct_l + (size_t)bs*RR*NN + nb,        NN,
                     64, sm, sb, acc);
    store_acc(sm, acc);
    __syncthreads();
    float* Ct = (float*)sm;
    int d = tid >> 1, h = tid & 1;
    float* out = g_numB + (bs*DD + d0 + d)*RR + h*32;
    #pragma unroll
    for (int j = 0; j < 32; j++) atomicAdd(&out[j], Ct[d*72 + h*32 + j]);
}

// ---------- b update ----------
__global__ void __launch_bounds__(128) k_bupdate(int selIn, int selOut){
    int r = blockIdx.x, bs = blockIdx.y, tid = threadIdx.x;
    __shared__ float ctcCol[64], red[128];
    const float* bin = bsel(selIn) + bs*DD*RR;
    float* bout = bsel(selOut) + bs*DD*RR;
    const float* nb = g_numB + bs*DD*RR;
    if (tid < 64) ctcCol[tid] = g_CtC[bs*RR*RR + tid*RR + r];
    __syncthreads();
    float v[4], ss = 0.f;
    #pragma unroll
    for (int q = 0; q < 4; q++){
        int d = tid + q*128; const float* brow = bin + d*RR;
        float den = EPSF;
        #pragma unroll 8
        for (int s = 0; s < RR; s++) den = fmaf(brow[s], ctcCol[s], den);
        float t = fmaxf(brow[r] * nb[d*RR + r] / den, EPSF);
        v[q] = t; ss += t*t;
    }
    red[tid] = ss; __syncthreads();
    for (int o = 64; o > 0; o >>= 1){ if (tid < o) red[tid] += red[tid+o]; __syncthreads(); }
    float inv = 1.f / fmaxf(sqrtf(red[0]), 1e-12f);
    #pragma unroll
    for (int q = 0; q < 4; q++){
        int d = tid + q*128;
        float w = v[q] * inv;
        bout[d*RR + r] = w;
        unsigned short h, l; split2(w, h, l);
        g_bt_h[(bs*RR+r)*DD + d] = __ushort_as_bfloat16(h);
        g_bt_l[(bs*RR+r)*DD + d] = __ushort_as_bfloat16(l);
        g_bn_h[(bs*DD+d)*RR + r] = __ushort_as_bfloat16(h);
        g_bn_l[(bs*DD+d)*RR + r] = __ushort_as_bfloat16(l);
    }
}

// ---------- x_hat ----------
__global__ void __launch_bounds__(256) k_xhat(float* __restrict__ out){
    extern __shared__ char sm[];
    uint32_t sb = smem_u32(sm);
    int bs = blockIdx.z, d0 = blockIdx.y*128, n0 = blockIdx.x*64, tid = threadIdx.x;
    AccFrag acc[2][2];
    gemm_core<false>(g_bn_h + (bs*DD + d0)*RR,         g_bn_l + (bs*DD + d0)*RR,         RR,
                     g_cn_h + ((size_t)bs*NN + n0)*RR, g_cn_l + ((size_t)bs*NN + n0)*RR, RR,
                     2, sm, sb, acc);
    store_acc(sm, acc);
    __syncthreads();
    float* Ct = (float*)sm;
    int d = tid >> 1, h = tid & 1;
    float* orow = out + (size_t)(bs*DD + d0 + d)*NN + n0 + h*32;
    #pragma unroll
    for (int j4 = 0; j4 < 32; j4 += 4)
        *(float4*)(orow + j4) = make_float4(Ct[d*72+h*32+j4], Ct[d*72+h*32+j4+1], Ct[d*72+h*32+j4+2], Ct[d*72+h*32+j4+3]);
}

// ---------- orchestration ----------
extern "C" void kernel_launch(void* const* d_in, const int* in_sizes, int n_in,
                              void* d_out, int out_size){
    const float* x = (const float*)d_in[0];
    const float* bases = (const float*)d_in[1];
    float* out = (float*)d_out;

    cudaFuncSetAttribute(k_cmma<0>, cudaFuncAttributeMaxDynamicSharedMemorySize, SMEMG);
    cudaFuncSetAttribute(k_cmma<1>, cudaFuncAttributeMaxDynamicSharedMemorySize, SMEMG);
    cudaFuncSetAttribute(k_cmma<2>, cudaFuncAttributeMaxDynamicSharedMemorySize, SMEMG);
    cudaFuncSetAttribute(k_numBmma, cudaFuncAttributeMaxDynamicSharedMemorySize, SMEMG);
    cudaFuncSetAttribute(k_xhat,    cudaFuncAttributeMaxDynamicSharedMemorySize, SMEMG);

    k_prep<<<16384, 256>>>(x);
    k_normb<<<BS*RR, 128>>>(bases);
    int sel = 0;
    k_cmma<0><<<dim3(NN/128, BS), 256, SMEMG>>>(0);
    for (int step = 0; step < 6; step++){
        k_zero<<<256, 256>>>();
        k_btb<<<dim3(8, BS), 256>>>(sel);
        k_cmma<1><<<dim3(NN/128, BS), 256, SMEMG>>>(step > 0 ? 1 : 0);
        k_numBmma<<<dim3(32, DD/128, BS), 256, SMEMG>>>();
        k_bupdate<<<dim3(RR, BS), 128>>>(sel, 1 - sel);
        sel = 1 - sel;
    }
    k_zero<<<256, 256>>>();
    k_btb<<<dim3(8, BS), 256>>>(sel);
    k_cmma<2><<<dim3(NN/128, BS), 256, SMEMG>>>(1);
    k_xhat<<<dim3(NN/64, DD/128, BS), 256, SMEMG>>>(out);
}